// round 1
// baseline (speedup 1.0000x reference)
#include <cuda_runtime.h>

// Shapes (fixed by the problem):
//   image_patches [64, 576, 768]  -- DEAD (softmax over kv_len=1 -> attn==1)
//   cnn           [64, 2048]
//   Wq            [768, 768]      -- DEAD
//   Wkv           [2048, 1536]    (k = cols [0,768), v = cols [768,1536))
//   Wp            [768, 768]
//   bp            [768]
//   out           [64, 576, 768]  = broadcast_n( (cnn @ Wkv[:,768:]) @ Wp + bp )

#define B_SZ   64
#define N_SEQ  576
#define C_DIM  768
#define K1     2048
#define LDKV   1536
#define NT     12        // 768 / 64 column tiles
#define KSPLIT1 32
#define KCHUNK1 64       // 2048 / 32
#define KSPLIT2 12
#define KCHUNK2 64       // 768 / 12

// Scratch (no allocations allowed -> __device__ globals)
__device__ float g_p1[KSPLIT1 * B_SZ * C_DIM];   // GEMM1 split-K partials (6.3 MB)
__device__ float g_v [B_SZ * C_DIM];             // v = cnn @ Wkv[:,768:]
__device__ float g_p2[KSPLIT2 * B_SZ * C_DIM];   // GEMM2 split-K partials (2.25 MB)

// ---------------------------------------------------------------------------
// Tile GEMM: computes P[64 x 64] = A[64 x kchunk] * Bm[kchunk x 64]
// A base points at (row 0, k-start), lda given. Bm base points at (k-start, n0).
// 256 threads: 16x16 grid, each thread owns a 4x4 micro-tile.
// ---------------------------------------------------------------------------
__device__ __forceinline__ void gemm_tile(
    const float* __restrict__ A, int lda,
    const float* __restrict__ Bm, int ldb,
    int kchunk, float* __restrict__ Pout)
{
    __shared__ float As[16][65];   // transposed A tile (pad 65 kills STS conflicts)
    __shared__ float Bs[16][64];

    const int tid = threadIdx.x;
    const int tx = tid & 15;
    const int ty = tid >> 4;

    float acc[4][4] = {};

    for (int kt = 0; kt < kchunk; kt += 16) {
        // Load A tile 64x16 (coalesced float4 per thread), store transposed.
        {
            int m  = tid >> 2;            // 0..63
            int kq = (tid & 3) * 4;       // 0,4,8,12
            float4 a = *(const float4*)&A[m * lda + kt + kq];
            As[kq + 0][m] = a.x;
            As[kq + 1][m] = a.y;
            As[kq + 2][m] = a.z;
            As[kq + 3][m] = a.w;
        }
        // Load B tile 16x64 (coalesced float4).
        {
            int k  = tid >> 4;            // 0..15
            int n4 = (tid & 15) * 4;      // 0..60
            *(float4*)&Bs[k][n4] = *(const float4*)&Bm[(kt + k) * ldb + n4];
        }
        __syncthreads();

        #pragma unroll
        for (int k = 0; k < 16; ++k) {
            float a0 = As[k][ty * 4 + 0];
            float a1 = As[k][ty * 4 + 1];
            float a2 = As[k][ty * 4 + 2];
            float a3 = As[k][ty * 4 + 3];
            float4 b = *(const float4*)&Bs[k][tx * 4];
            acc[0][0] += a0 * b.x; acc[0][1] += a0 * b.y; acc[0][2] += a0 * b.z; acc[0][3] += a0 * b.w;
            acc[1][0] += a1 * b.x; acc[1][1] += a1 * b.y; acc[1][2] += a1 * b.z; acc[1][3] += a1 * b.w;
            acc[2][0] += a2 * b.x; acc[2][1] += a2 * b.y; acc[2][2] += a2 * b.z; acc[2][3] += a2 * b.w;
            acc[3][0] += a3 * b.x; acc[3][1] += a3 * b.y; acc[3][2] += a3 * b.z; acc[3][3] += a3 * b.w;
        }
        __syncthreads();
    }

    #pragma unroll
    for (int i = 0; i < 4; ++i) {
        float4 r = make_float4(acc[i][0], acc[i][1], acc[i][2], acc[i][3]);
        *(float4*)&Pout[(ty * 4 + i) * C_DIM + tx * 4] = r;
    }
}

// GEMM1: v partials = cnn[64,2048] @ Wkv[:, 768:1536]
__global__ void __launch_bounds__(256, 4)
gemm1_kernel(const float* __restrict__ cnn, const float* __restrict__ Wkv)
{
    int ntile = blockIdx.x % NT;
    int split = blockIdx.x / NT;
    int n0 = ntile * 64;
    const float* A  = cnn + split * KCHUNK1;                       // column offset in K
    const float* Bm = Wkv + (size_t)(split * KCHUNK1) * LDKV + C_DIM + n0;
    gemm_tile(A, K1, Bm, LDKV, KCHUNK1, g_p1 + split * (B_SZ * C_DIM) + n0);
}

// Reduce GEMM1 partials -> g_v
__global__ void reduce1_kernel()
{
    int idx = blockIdx.x * blockDim.x + threadIdx.x;   // float4 index, 12288 total
    const float4* p = (const float4*)g_p1;
    float4 s = make_float4(0.f, 0.f, 0.f, 0.f);
    #pragma unroll
    for (int sp = 0; sp < KSPLIT1; ++sp) {
        float4 t = p[sp * (B_SZ * C_DIM / 4) + idx];
        s.x += t.x; s.y += t.y; s.z += t.z; s.w += t.w;
    }
    ((float4*)g_v)[idx] = s;
}

// GEMM2: y partials = v[64,768] @ Wp[768,768]
__global__ void __launch_bounds__(256, 4)
gemm2_kernel(const float* __restrict__ Wp)
{
    int ntile = blockIdx.x % NT;
    int split = blockIdx.x / NT;
    int n0 = ntile * 64;
    gemm_tile(g_v + split * KCHUNK2, C_DIM,
              Wp + (size_t)(split * KCHUNK2) * C_DIM + n0, C_DIM,
              KCHUNK2, g_p2 + split * (B_SZ * C_DIM) + n0);
}

// Reduce GEMM2 partials + bias, then broadcast over N=576. DRAM-write bound.
// grid = 64 batches * 8 n-chunks (72 rows each); block = 192 threads (768/4 cols)
__global__ void __launch_bounds__(192)
bcast_kernel(const float* __restrict__ bp, float* __restrict__ out)
{
    int b      = blockIdx.x >> 3;
    int nchunk = blockIdx.x & 7;
    int c4     = threadIdx.x;                 // float4 column index 0..191

    const float4* p2 = (const float4*)g_p2;
    float4 y = ((const float4*)bp)[c4];
    int base = b * (C_DIM / 4) + c4;
    #pragma unroll
    for (int s = 0; s < KSPLIT2; ++s) {
        float4 t = p2[s * (B_SZ * C_DIM / 4) + base];
        y.x += t.x; y.y += t.y; y.z += t.z; y.w += t.w;
    }

    float4* o = (float4*)out + (size_t)(b * N_SEQ + nchunk * 72) * (C_DIM / 4) + c4;
    #pragma unroll 8
    for (int n = 0; n < 72; ++n) {
        *o = y;
        o += C_DIM / 4;
    }
}

extern "C" void kernel_launch(void* const* d_in, const int* in_sizes, int n_in,
                              void* d_out, int out_size)
{
    (void)in_sizes; (void)n_in; (void)out_size;
    // Input order per metadata: image_patches, cnn_feature_vector, Wq, Wkv, Wp, bp
    const float* cnn = (const float*)d_in[1];
    const float* Wkv = (const float*)d_in[3];
    const float* Wp  = (const float*)d_in[4];
    const float* bp  = (const float*)d_in[5];
    float* out = (float*)d_out;

    gemm1_kernel<<<NT * KSPLIT1, 256>>>(cnn, Wkv);
    reduce1_kernel<<<(B_SZ * C_DIM / 4) / 256, 256>>>();
    gemm2_kernel<<<NT * KSPLIT2, 256>>>(Wp);
    bcast_kernel<<<B_SZ * 8, 192>>>(bp, out);
}